// round 1
// baseline (speedup 1.0000x reference)
#include <cuda_runtime.h>
#include <math.h>

// Scratch for x_proj: B*N rows x L cols (max 8192 x 256)
#define MAX_BN 8192
#define MAX_L  256
__device__ float g_xp[MAX_BN * MAX_L];

// ---------- helpers: order-preserving float<->uint key ----------
__device__ __forceinline__ unsigned f2key(float f) {
    unsigned u = __float_as_uint(f);
    return (u & 0x80000000u) ? ~u : (u | 0x80000000u);
}
__device__ __forceinline__ float key2f(unsigned k) {
    unsigned u = (k & 0x80000000u) ? (k & 0x7fffffffu) : ~k;
    return __uint_as_float(u);
}

// ---------- Kernel 1: x_proj = x @ W^T  (out rows = B*N, cols = L) ----------
__global__ void proj_kernel(const float* __restrict__ x,
                            const float* __restrict__ W,
                            int BN, int L) {
    __shared__ float xs[8 * 256];
    int n0 = blockIdx.x * 8;
    int rows = min(8, BN - n0);
    int t = threadIdx.x;
    for (int i = t; i < rows * L; i += 256) xs[i] = x[(size_t)n0 * L + i];
    __syncthreads();
    if (t < L) {
        float acc[8];
#pragma unroll
        for (int r = 0; r < 8; r++) acc[r] = 0.f;
        for (int l = 0; l < L; l++) {
            float w = W[(size_t)t * L + l];
#pragma unroll
            for (int r = 0; r < 8; r++) acc[r] += xs[r * L + l] * w;
        }
        for (int r = 0; r < rows; r++)
            g_xp[(size_t)(n0 + r) * L + t] = acc[r];
    }
}

// ---------- Kernel 2: score = XP @ XP^T per batch, written into attn region ----------
__global__ void score_kernel(float* __restrict__ S, int N, int L) {
    int b  = blockIdx.z;
    const float* base = g_xp + (size_t)b * N * L;
    int i0 = blockIdx.y * 64, j0 = blockIdx.x * 64;
    __shared__ float As[8][65];
    __shared__ float Bs[8][65];
    int tid = threadIdx.x;
    int tx = tid & 15, ty = tid >> 4;
    float acc[4][4];
#pragma unroll
    for (int a = 0; a < 4; a++)
#pragma unroll
        for (int c = 0; c < 4; c++) acc[a][c] = 0.f;

    for (int k0 = 0; k0 < L; k0 += 8) {
#pragma unroll
        for (int i = 0; i < 2; i++) {
            int idx = tid + i * 256;
            int r = idx >> 3, c = idx & 7;
            int kk = k0 + c;
            float av = 0.f, bv = 0.f;
            if (kk < L) {
                if (i0 + r < N) av = base[(size_t)(i0 + r) * L + kk];
                if (j0 + r < N) bv = base[(size_t)(j0 + r) * L + kk];
            }
            As[c][r] = av;
            Bs[c][r] = bv;
        }
        __syncthreads();
#pragma unroll
        for (int k = 0; k < 8; k++) {
            float ra[4], rb[4];
#pragma unroll
            for (int a = 0; a < 4; a++) ra[a] = As[k][ty * 4 + a];
#pragma unroll
            for (int c = 0; c < 4; c++) rb[c] = Bs[k][tx * 4 + c];
#pragma unroll
            for (int a = 0; a < 4; a++)
#pragma unroll
                for (int c = 0; c < 4; c++) acc[a][c] += ra[a] * rb[c];
        }
        __syncthreads();
    }
#pragma unroll
    for (int a = 0; a < 4; a++) {
        int i = i0 + ty * 4 + a;
        if (i >= N) continue;
        float* row = S + ((size_t)b * N + i) * N + j0;
#pragma unroll
        for (int c = 0; c < 4; c++) {
            int j = j0 + tx * 4 + c;
            if (j < N) row[tx * 4 + c] = acc[a][c];
        }
    }
}

// ---------- Kernel 3: per-row topk selection + masked softmax + sparse h ----------
// One block (256 threads) per global row n in [0, B*N).
// Dynamic smem: N words, first holding keys, then overwritten with v / e / a.
__global__ void attn_kernel(float* __restrict__ h_out,
                            float* __restrict__ attn,
                            int N, int L) {
    extern __shared__ unsigned su[];
    float* sf = (float*)su;
    __shared__ float redf[256];
    __shared__ int   warp_tot[8];
    __shared__ int   s_cnt;
    __shared__ int   s_nnz;
    __shared__ int   ilist[1024];
    const int K = 100;

    int n = blockIdx.x;
    int b = n / N;
    int diag = n - b * N;
    int t = threadIdx.x;
    int lane = t & 31, w = t >> 5;
    float* row = attn + (size_t)n * N;

    // load keys
    for (int m = t; m < N; m += 256) su[m] = f2key(row[m]);
    __syncthreads();

    // radix binary search: res = key of the K-th largest element
    unsigned res = 0u;
    for (int bit = 31; bit >= 0; --bit) {
        unsigned cand = res | (1u << bit);
        if (t == 0) s_cnt = 0;
        __syncthreads();
        int c = 0;
        for (int m = t; m < N; m += 256) c += (su[m] >= cand) ? 1 : 0;
#pragma unroll
        for (int o = 16; o; o >>= 1) c += __shfl_down_sync(0xffffffffu, c, o);
        if (lane == 0) atomicAdd(&s_cnt, c);
        __syncthreads();
        if (s_cnt >= K) res = cand;
        __syncthreads();
    }

    // count strictly-greater; need = how many ties (==res) become neighbors
    if (t == 0) s_cnt = 0;
    __syncthreads();
    {
        int c = 0;
        for (int m = t; m < N; m += 256) c += (su[m] > res) ? 1 : 0;
#pragma unroll
        for (int o = 16; o; o >>= 1) c += __shfl_down_sync(0xffffffffu, c, o);
        if (lane == 0) atomicAdd(&s_cnt, c);
    }
    __syncthreads();
    int need = K - s_cnt;   // ties taken in ascending index order (jax top_k order)
    __syncthreads();

    // tie-ordered scan, compute masked value v, track max
    int running = 0;
    float vmax = -3.4e38f;
    for (int m0 = 0; m0 < N; m0 += 256) {
        int m = m0 + t;
        bool valid = (m < N);
        unsigned u = valid ? su[m] : 0u;
        bool eq = valid && (u == res);
        unsigned ball = __ballot_sync(0xffffffffu, eq);
        if (lane == 0) warp_tot[w] = __popc(ball);
        __syncthreads();
        int woff = 0, ctot = 0;
#pragma unroll
        for (int i = 0; i < 8; i++) {
            int wt = warp_tot[i];
            ctot += wt;
            if (i < w) woff += wt;
        }
        int rank = running + woff + __popc(ball & ((1u << lane) - 1u));
        if (valid) {
            bool nb = (u > res) || (eq && rank < need) || (m == diag);
            float s = key2f(u);
            float v = nb ? s : (-1e19f * s);
            sf[m] = v;
            vmax = fmaxf(vmax, v);
        }
        running += ctot;
        __syncthreads();
    }

    // block max (deterministic tree)
    redf[t] = vmax;
    __syncthreads();
#pragma unroll
    for (int stride = 128; stride; stride >>= 1) {
        if (t < stride) redf[t] = fmaxf(redf[t], redf[t + stride]);
        __syncthreads();
    }
    float M = redf[0];
    __syncthreads();

    // exp + deterministic sum
    float lsum = 0.f;
    for (int m = t; m < N; m += 256) {
        float e = expf(sf[m] - M);
        sf[m] = e;
        lsum += e;
    }
    __syncthreads();
    redf[t] = lsum;
    __syncthreads();
#pragma unroll
    for (int stride = 128; stride; stride >>= 1) {
        if (t < stride) redf[t] += redf[t + stride];
        __syncthreads();
    }
    float inv = 1.0f / redf[0];
    __syncthreads();

    // normalize, write attention, gather nonzeros (exact: exp underflow -> 0)
    if (t == 0) s_nnz = 0;
    __syncthreads();
    for (int m = t; m < N; m += 256) {
        float a = sf[m] * inv;
        sf[m] = a;
        row[m] = a;
        if (a != 0.f) {
            int p = atomicAdd(&s_nnz, 1);
            if (p < 1024) ilist[p] = m;
        }
    }
    __syncthreads();
    int nnz = s_nnz;

    // h[n,:] = sum over nonzero attention entries
    if (t < L) {
        const float* xpb = g_xp + (size_t)b * N * L;
        float acc = 0.f;
        if (nnz == 1) {
            int m = ilist[0];
            acc = sf[m] * xpb[(size_t)m * L + t];
        } else if (nnz <= 1024) {
            // deterministic order: walk all N, add nonzeros in index order
            for (int m = 0; m < N; m++) {
                float a = sf[m];
                if (a != 0.f) acc += a * xpb[(size_t)m * L + t];
            }
        } else {
            for (int m = 0; m < N; m++) acc += sf[m] * xpb[(size_t)m * L + t];
        }
        h_out[(size_t)n * L + t] = acc;
    }
}

// ---------- launch ----------
extern "C" void kernel_launch(void* const* d_in, const int* in_sizes, int n_in,
                              void* d_out, int out_size) {
    const float* x = (const float*)d_in[0];
    const float* W = (const float*)d_in[1];

    // derive dims: in_sizes[1] = L*L ; in_sizes[0] = B*N*L ; out = B*N*L + B*N*N
    int L = (int)(sqrt((double)in_sizes[1]) + 0.5);
    long long BN = in_sizes[0] / L;                 // B*N
    long long N  = (long long)out_size / BN - L;    // patches per bag
    int Ni = (int)N;
    int B  = (int)(BN / N);
    int BNi = (int)BN;

    float* h_out = (float*)d_out;
    float* attn  = h_out + (size_t)BN * L;

    // 1) projection
    int pb = (BNi + 7) / 8;
    proj_kernel<<<pb, 256>>>(x, W, BNi, L);

    // 2) score GEMM into attention region
    dim3 g2((Ni + 63) / 64, (Ni + 63) / 64, B);
    score_kernel<<<g2, 256>>>(attn, Ni, L);

    // 3) per-row select + softmax + h
    size_t smem = (size_t)Ni * sizeof(float);
    attn_kernel<<<BNi, 256, smem>>>(h_out, attn, Ni, L);
}

// round 3
// speedup vs baseline: 2.5583x; 2.5583x over previous
#include <cuda_runtime.h>
#include <math.h>
#include <cstdint>

#define MAX_BN 8192
#define MAX_L  256
__device__ float g_xp[MAX_BN * MAX_L];
__device__ int   g_flags[MAX_BN];

// ---------- helpers: order-preserving float<->uint key (slow path) ----------
__device__ __forceinline__ unsigned f2key(float f) {
    unsigned u = __float_as_uint(f);
    return (u & 0x80000000u) ? ~u : (u | 0x80000000u);
}
__device__ __forceinline__ float key2f(unsigned k) {
    unsigned u = (k & 0x80000000u) ? (k & 0x7fffffffu) : ~k;
    return __uint_as_float(u);
}

// ---------- Kernel 1: x_proj = x @ W^T (coalesced W via smem transpose tiles) ----
#define PROJ_ROWS 8
__global__ void proj_kernel(const float* __restrict__ x,
                            const float* __restrict__ W,
                            int BN, int L) {
    __shared__ float xs[PROJ_ROWS * 256];
    __shared__ float Ws[32][257];   // Ws[l][o]
    int n0 = blockIdx.x * PROJ_ROWS;
    int rows = min(PROJ_ROWS, BN - n0);
    int t = threadIdx.x;
    for (int i = t; i < rows * L; i += 256) xs[i] = x[(size_t)n0 * L + i];

    float acc[PROJ_ROWS];
#pragma unroll
    for (int r = 0; r < PROJ_ROWS; r++) acc[r] = 0.f;

    for (int l0 = 0; l0 < L; l0 += 32) {
        int lw = min(32, L - l0);
        __syncthreads();
        for (int idx = t; idx < L * lw; idx += 256) {
            int o = idx / lw, l = idx - o * lw;
            Ws[l][o] = W[(size_t)o * L + l0 + l];
        }
        __syncthreads();
        if (t < L) {
            for (int l = 0; l < lw; l++) {
                float w = Ws[l][t];
#pragma unroll
                for (int r = 0; r < PROJ_ROWS; r++)
                    acc[r] += xs[r * L + l0 + l] * w;
            }
        }
    }
    if (t < L)
        for (int r = 0; r < rows; r++)
            g_xp[(size_t)(n0 + r) * L + t] = acc[r];
}

// ---------- Kernel 2: symmetric score GEMM, 128x128 tiles, double-buffered ----
__device__ __forceinline__ float4 ldxp4(const float* __restrict__ base,
                                        int row, int k, int N, int L) {
    float4 v = make_float4(0.f, 0.f, 0.f, 0.f);
    if (row < N) {
        const float* p = base + (size_t)row * L + k;
        if (k + 3 < L) {
            if ((((unsigned long long)(uintptr_t)p) & 15ull) == 0)
                v = *(const float4*)p;
            else { v.x = p[0]; v.y = p[1]; v.z = p[2]; v.w = p[3]; }
        } else {
            if (k     < L) v.x = p[0];
            if (k + 1 < L) v.y = p[1];
            if (k + 2 < L) v.z = p[2];
        }
    }
    return v;
}

__global__ __launch_bounds__(256, 2)
void score_kernel(float* __restrict__ S, int N, int L, int nb) {
    int b = blockIdx.y;
    const float* base = g_xp + (size_t)b * N * L;

    // triangular block mapping (bj >= bi)
    int t = blockIdx.x;
    int bi;
    {
        float fnb = (float)(2 * nb + 1);
        int est = (int)((fnb - sqrtf(fnb * fnb - 8.0f * (float)t)) * 0.5f);
        if (est < 0) est = 0;
        if (est >= nb) est = nb - 1;
        bi = est;
        while (bi > 0 && (bi * nb - bi * (bi - 1) / 2) > t) bi--;
        while (((bi + 1) * nb - (bi + 1) * bi / 2) <= t) bi++;
    }
    int bj = bi + (t - (bi * nb - bi * (bi - 1) / 2));
    int i0 = bi * 128, j0 = bj * 128;

    __shared__ __align__(16) float As[2][8][128];
    __shared__ __align__(16) float Bs[2][8][128];
    __shared__ __align__(16) float Tr[16][132];

    int tid = threadIdx.x;
    int tx = tid & 15, ty = tid >> 4;
    int lr = tid >> 1;            // 0..127
    int lh = (tid & 1) * 4;       // 0 or 4

    float acc[8][8];
#pragma unroll
    for (int a = 0; a < 8; a++)
#pragma unroll
        for (int c = 0; c < 8; c++) acc[a][c] = 0.f;

    int nk = (L + 7) / 8;

    // prefetch chunk 0
    {
        float4 av = ldxp4(base, i0 + lr, lh, N, L);
        float4 bv = ldxp4(base, j0 + lr, lh, N, L);
        As[0][lh + 0][lr] = av.x; As[0][lh + 1][lr] = av.y;
        As[0][lh + 2][lr] = av.z; As[0][lh + 3][lr] = av.w;
        Bs[0][lh + 0][lr] = bv.x; Bs[0][lh + 1][lr] = bv.y;
        Bs[0][lh + 2][lr] = bv.z; Bs[0][lh + 3][lr] = bv.w;
    }
    __syncthreads();

    int buf = 0;
    for (int kc = 0; kc < nk; kc++) {
        float4 an, bn;
        bool has = (kc + 1 < nk);
        if (has) {
            an = ldxp4(base, i0 + lr, (kc + 1) * 8 + lh, N, L);
            bn = ldxp4(base, j0 + lr, (kc + 1) * 8 + lh, N, L);
        }
#pragma unroll
        for (int k = 0; k < 8; k++) {
            float4 ra0 = *(const float4*)&As[buf][k][ty * 8];
            float4 ra1 = *(const float4*)&As[buf][k][ty * 8 + 4];
            float4 rb0 = *(const float4*)&Bs[buf][k][tx * 8];
            float4 rb1 = *(const float4*)&Bs[buf][k][tx * 8 + 4];
            float ra[8] = {ra0.x, ra0.y, ra0.z, ra0.w, ra1.x, ra1.y, ra1.z, ra1.w};
            float rb[8] = {rb0.x, rb0.y, rb0.z, rb0.w, rb1.x, rb1.y, rb1.z, rb1.w};
#pragma unroll
            for (int a = 0; a < 8; a++)
#pragma unroll
                for (int c = 0; c < 8; c++)
                    acc[a][c] += ra[a] * rb[c];
        }
        if (has) {
            int nb2 = buf ^ 1;
            As[nb2][lh + 0][lr] = an.x; As[nb2][lh + 1][lr] = an.y;
            As[nb2][lh + 2][lr] = an.z; As[nb2][lh + 3][lr] = an.w;
            Bs[nb2][lh + 0][lr] = bn.x; Bs[nb2][lh + 1][lr] = bn.y;
            Bs[nb2][lh + 2][lr] = bn.z; Bs[nb2][lh + 3][lr] = bn.w;
        }
        __syncthreads();
        buf ^= 1;
    }

    // store normal block (i rows, j cols)
#pragma unroll
    for (int a = 0; a < 8; a++) {
        int i = i0 + ty * 8 + a;
        if (i < N) {
            float* rowp = S + (size_t)b * N * N + (size_t)i * N + j0 + tx * 8;
            if (j0 + tx * 8 + 7 < N) {
                *(float4*)rowp       = make_float4(acc[a][0], acc[a][1], acc[a][2], acc[a][3]);
                *(float4*)(rowp + 4) = make_float4(acc[a][4], acc[a][5], acc[a][6], acc[a][7]);
            } else {
                for (int c = 0; c < 8; c++)
                    if (j0 + tx * 8 + c < N) rowp[c] = acc[a][c];
            }
        }
    }

    // mirror (transposed) store for off-diagonal blocks, staged via smem
    if (bi != bj) {
#pragma unroll 1
        for (int s = 0; s < 8; s++) {   // j-strip of 16
            __syncthreads();
            if ((tx >> 1) == s) {
                int cbase = (tx & 1) * 8;
#pragma unroll
                for (int c = 0; c < 8; c++)
#pragma unroll
                    for (int a = 0; a < 8; a++)
                        Tr[cbase + c][ty * 8 + a] = acc[a][c];
            }
            __syncthreads();
            int jr = tid >> 4;            // 0..15
            int ic = (tid & 15) * 8;      // 0..120
            int jrow = j0 + s * 16 + jr;
            if (jrow < N) {
                float* outp = S + (size_t)b * N * N + (size_t)jrow * N + i0 + ic;
                if (i0 + ic + 7 < N) {
                    *(float4*)outp       = *(const float4*)&Tr[jr][ic];
                    *(float4*)(outp + 4) = *(const float4*)&Tr[jr][ic + 4];
                } else {
                    for (int q = 0; q < 8; q++)
                        if (i0 + ic + q < N) outp[q] = Tr[jr][ic + q];
                }
            }
        }
    }
}

// ---------- Kernel 3a: fast path — exact one-hot softmax at row argmin ----------
__global__ void attn_fast_kernel(float* __restrict__ h_out,
                                 float* __restrict__ attn,
                                 int N, int L, int K) {
    extern __shared__ float sf[];
    __shared__ float red[256];
    __shared__ int s_cnt, s_idx;

    int n = blockIdx.x;
    int b = n / N;
    int t = threadIdx.x;
    int lane = t & 31;
    float* row = attn + (size_t)n * N;

    float lmin = 3.4e38f, lmax = -3.4e38f;
    for (int m = t; m < N; m += 256) {
        float v = row[m];
        sf[m] = v;
        lmin = fminf(lmin, v);
        lmax = fmaxf(lmax, v);
    }
    // block min
    red[t] = lmin; __syncthreads();
#pragma unroll
    for (int st = 128; st; st >>= 1) { if (t < st) red[t] = fminf(red[t], red[t + st]); __syncthreads(); }
    float fmin = red[0]; __syncthreads();
    // block max
    red[t] = lmax; __syncthreads();
#pragma unroll
    for (int st = 128; st; st >>= 1) { if (t < st) red[t] = fmaxf(red[t], red[t + st]); __syncthreads(); }
    float fmax = red[0]; __syncthreads();
    // second-smallest distinct value
    float lmin2 = 3.4e38f;
    for (int m = t; m < N; m += 256) { float v = sf[m]; if (v > fmin) lmin2 = fminf(lmin2, v); }
    red[t] = lmin2; __syncthreads();
#pragma unroll
    for (int st = 128; st; st >>= 1) { if (t < st) red[t] = fminf(red[t], red[t + st]); __syncthreads(); }
    float fmin2 = red[0];
    // tie count + smallest tie index
    if (t == 0) { s_cnt = 0; s_idx = N; }
    __syncthreads();
    {
        int c = 0;
        for (int m = t; m < N; m += 256)
            if (sf[m] == fmin) { c++; atomicMin(&s_idx, m); }
#pragma unroll
        for (int o = 16; o; o >>= 1) c += __shfl_down_sync(0xffffffffu, c, o);
        if (lane == 0) atomicAdd(&s_cnt, c);
    }
    __syncthreads();
    int c = s_cnt;
    int idx0 = s_idx;

    // guards for exact one-hot equivalence with the reference masked softmax
    bool ok = (fmin < 0.f)
           && (-fmin > (fmax + 256.f) * 1e-19f)     // neighbor terms underflow exactly
           && (fmin2 - fmin > 3e-17f)               // non-neighbor gap underflows exactly
           && (c <= 16) && (c <= N - K);            // argmin cannot be a top-k neighbor

    if (t == 0) g_flags[n] = ok ? 0 : 1;
    if (!ok) return;

    float a1 = 1.0f / (float)c;
    for (int m = t; m < N; m += 256)
        row[m] = (sf[m] == fmin) ? a1 : 0.f;

    if (t < L) {
        const float* xpb = g_xp + (size_t)b * N * L;
        float accv;
        if (c == 1) {
            accv = xpb[(size_t)idx0 * L + t];
        } else {
            accv = 0.f;
            for (int m = 0; m < N; m++)
                if (sf[m] == fmin) accv += a1 * xpb[(size_t)m * L + t];
        }
        h_out[(size_t)n * L + t] = accv;
    }
}

// ---------- Kernel 3b: general fallback (flag-gated, early exit) ----------
__global__ void attn_slow_kernel(float* __restrict__ h_out,
                                 float* __restrict__ attn,
                                 int N, int L) {
    int n = blockIdx.x;
    if (g_flags[n] == 0) return;

    extern __shared__ unsigned su[];
    float* sf = (float*)su;
    __shared__ float redf[256];
    __shared__ int   warp_tot[8];
    __shared__ int   s_cnt;
    __shared__ int   s_nnz;
    __shared__ int   ilist[1024];
    const int K = 100;

    int b = n / N;
    int diag = n - b * N;
    int t = threadIdx.x;
    int lane = t & 31, w = t >> 5;
    float* row = attn + (size_t)n * N;

    for (int m = t; m < N; m += 256) su[m] = f2key(row[m]);
    __syncthreads();

    unsigned res = 0u;
    for (int bit = 31; bit >= 0; --bit) {
        unsigned cand = res | (1u << bit);
        if (t == 0) s_cnt = 0;
        __syncthreads();
        int c = 0;
        for (int m = t; m < N; m += 256) c += (su[m] >= cand) ? 1 : 0;
#pragma unroll
        for (int o = 16; o; o >>= 1) c += __shfl_down_sync(0xffffffffu, c, o);
        if (lane == 0) atomicAdd(&s_cnt, c);
        __syncthreads();
        if (s_cnt >= K) res = cand;
        __syncthreads();
    }

    if (t == 0) s_cnt = 0;
    __syncthreads();
    {
        int c = 0;
        for (int m = t; m < N; m += 256) c += (su[m] > res) ? 1 : 0;
#pragma unroll
        for (int o = 16; o; o >>= 1) c += __shfl_down_sync(0xffffffffu, c, o);
        if (lane == 0) atomicAdd(&s_cnt, c);
    }
    __syncthreads();
    int need = K - s_cnt;
    __syncthreads();

    int running = 0;
    float vmax = -3.4e38f;
    for (int m0 = 0; m0 < N; m0 += 256) {
        int m = m0 + t;
        bool valid = (m < N);
        unsigned u = valid ? su[m] : 0u;
        bool eq = valid && (u == res);
        unsigned ball = __ballot_sync(0xffffffffu, eq);
        if (lane == 0) warp_tot[w] = __popc(ball);
        __syncthreads();
        int woff = 0, ctot = 0;
#pragma unroll
        for (int i = 0; i < 8; i++) {
            int wt = warp_tot[i];
            ctot += wt;
            if (i < w) woff += wt;
        }
        int rank = running + woff + __popc(ball & ((1u << lane) - 1u));
        if (valid) {
            bool nb = (u > res) || (eq && rank < need) || (m == diag);
            float s = key2f(u);
            float v = nb ? s : (-1e19f * s);
            sf[m] = v;
            vmax = fmaxf(vmax, v);
        }
        running += ctot;
        __syncthreads();
    }

    redf[t] = vmax; __syncthreads();
#pragma unroll
    for (int st = 128; st; st >>= 1) { if (t < st) redf[t] = fmaxf(redf[t], redf[t + st]); __syncthreads(); }
    float M = redf[0]; __syncthreads();

    float lsum = 0.f;
    for (int m = t; m < N; m += 256) {
        float e = expf(sf[m] - M);
        sf[m] = e;
        lsum += e;
    }
    __syncthreads();
    redf[t] = lsum; __syncthreads();
#pragma unroll
    for (int st = 128; st; st >>= 1) { if (t < st) redf[t] += redf[t + st]; __syncthreads(); }
    float inv = 1.0f / redf[0]; __syncthreads();

    if (t == 0) s_nnz = 0;
    __syncthreads();
    for (int m = t; m < N; m += 256) {
        float a = sf[m] * inv;
        sf[m] = a;
        row[m] = a;
        if (a != 0.f) {
            int p = atomicAdd(&s_nnz, 1);
            if (p < 1024) ilist[p] = m;
        }
    }
    __syncthreads();
    int nnz = s_nnz;

    if (t < L) {
        const float* xpb = g_xp + (size_t)b * N * L;
        float acc = 0.f;
        if (nnz == 1) {
            int m = ilist[0];
            acc = sf[m] * xpb[(size_t)m * L + t];
        } else {
            for (int m = 0; m < N; m++) {
                float a = sf[m];
                if (a != 0.f) acc += a * xpb[(size_t)m * L + t];
            }
        }
        h_out[(size_t)n * L + t] = acc;
    }
}

// ---------- launch ----------
extern "C" void kernel_launch(void* const* d_in, const int* in_sizes, int n_in,
                              void* d_out, int out_size) {
    const float* x = (const float*)d_in[0];
    const float* W = (const float*)d_in[1];

    int L = (int)(sqrt((double)in_sizes[1]) + 0.5);
    long long BN = in_sizes[0] / L;
    long long N  = (long long)out_size / BN - L;
    int Ni = (int)N;
    int B  = (int)(BN / N);
    int BNi = (int)BN;

    float* h_out = (float*)d_out;
    float* attn  = h_out + (size_t)BN * L;

    // 1) projection
    proj_kernel<<<(BNi + PROJ_ROWS - 1) / PROJ_ROWS, 256>>>(x, W, BNi, L);

    // 2) symmetric score GEMM (upper-triangular blocks + mirrored stores)
    int nb = (Ni + 127) / 128;
    int tri = nb * (nb + 1) / 2;
    dim3 g2(tri, B);
    score_kernel<<<g2, 256>>>(attn, Ni, L, nb);

    // 3) fast one-hot path + guarded general fallback
    size_t smem = (size_t)Ni * sizeof(float);
    attn_fast_kernel<<<BNi, 256, smem>>>(h_out, attn, Ni, L, 100);
    attn_slow_kernel<<<BNi, 256, smem>>>(h_out, attn, Ni, L);
}

// round 4
// speedup vs baseline: 2.7288x; 1.0667x over previous
#include <cuda_runtime.h>
#include <math.h>
#include <cstdint>

#define MAX_BN 8192
#define MAX_L  256
#define MAX_NB 64
__device__ float g_xp[MAX_BN * MAX_L];
__device__ int   g_flags[MAX_BN];
__device__ int   g_argmin[MAX_BN];
// per-row per-blockcol partial stats
__device__ float g_pmin [MAX_BN * MAX_NB];
__device__ float g_pmin2[MAX_BN * MAX_NB];
__device__ float g_pmax [MAX_BN * MAX_NB];
__device__ int   g_pcnt [MAX_BN * MAX_NB];
__device__ int   g_pidx [MAX_BN * MAX_NB];

// ---------- helpers ----------
__device__ __forceinline__ unsigned f2key(float f) {
    unsigned u = __float_as_uint(f);
    return (u & 0x80000000u) ? ~u : (u | 0x80000000u);
}
__device__ __forceinline__ float key2f(unsigned k) {
    unsigned u = (k & 0x80000000u) ? (k & 0x7fffffffu) : ~k;
    return __uint_as_float(u);
}

// ---------- Kernel 1: x_proj = x @ W^T ----------
#define PROJ_ROWS 8
__global__ void proj_kernel(const float* __restrict__ x,
                            const float* __restrict__ W,
                            int BN, int L) {
    __shared__ float xs[PROJ_ROWS * 256];
    __shared__ float Ws[32][257];
    int n0 = blockIdx.x * PROJ_ROWS;
    int rows = min(PROJ_ROWS, BN - n0);
    int t = threadIdx.x;
    for (int i = t; i < rows * L; i += 256) xs[i] = x[(size_t)n0 * L + i];

    float acc[PROJ_ROWS];
#pragma unroll
    for (int r = 0; r < PROJ_ROWS; r++) acc[r] = 0.f;

    for (int l0 = 0; l0 < L; l0 += 32) {
        int lw = min(32, L - l0);
        __syncthreads();
        for (int idx = t; idx < L * lw; idx += 256) {
            int o = idx / lw, l = idx - o * lw;
            Ws[l][o] = W[(size_t)o * L + l0 + l];
        }
        __syncthreads();
        if (t < L) {
            for (int l = 0; l < lw; l++) {
                float w = Ws[l][t];
#pragma unroll
                for (int r = 0; r < PROJ_ROWS; r++)
                    acc[r] += xs[r * L + l0 + l] * w;
            }
        }
    }
    if (t < L)
        for (int r = 0; r < rows; r++)
            g_xp[(size_t)(n0 + r) * L + t] = acc[r];
}

// ---------- Kernel 2: symmetric score GEMM -> per-row strip statistics ----------
__device__ __forceinline__ float4 ldxp4(const float* __restrict__ base,
                                        int row, int k, int N, int L) {
    float4 v = make_float4(0.f, 0.f, 0.f, 0.f);
    if (row < N) {
        const float* p = base + (size_t)row * L + k;
        if (k + 3 < L) {
            if ((((unsigned long long)(uintptr_t)p) & 15ull) == 0)
                v = *(const float4*)p;
            else { v.x = p[0]; v.y = p[1]; v.z = p[2]; v.w = p[3]; }
        } else {
            if (k     < L) v.x = p[0];
            if (k + 1 < L) v.y = p[1];
            if (k + 2 < L) v.z = p[2];
        }
    }
    return v;
}

__global__ __launch_bounds__(256, 2)
void score_stats_kernel(int N, int L, int nb) {
    int b = blockIdx.y;
    const float* base = g_xp + (size_t)b * N * L;

    // triangular block mapping (bj >= bi)
    int t = blockIdx.x;
    int bi;
    {
        float fnb = (float)(2 * nb + 1);
        int est = (int)((fnb - sqrtf(fnb * fnb - 8.0f * (float)t)) * 0.5f);
        if (est < 0) est = 0;
        if (est >= nb) est = nb - 1;
        bi = est;
        while (bi > 0 && (bi * nb - bi * (bi - 1) / 2) > t) bi--;
        while (((bi + 1) * nb - (bi + 1) * bi / 2) <= t) bi++;
    }
    int bj = bi + (t - (bi * nb - bi * (bi - 1) / 2));
    int i0 = bi * 128, j0 = bj * 128;

    __shared__ __align__(16) float As[2][8][128];
    __shared__ __align__(16) float Bs[2][8][128];
    __shared__ float sred[128][17];
    __shared__ int   sredi[128][17];
    __shared__ float sminA[128];

    int tid = threadIdx.x;
    int tx = tid & 15, ty = tid >> 4;
    int lr = tid >> 1;
    int lh = (tid & 1) * 4;

    float acc[8][8];
#pragma unroll
    for (int a = 0; a < 8; a++)
#pragma unroll
        for (int c = 0; c < 8; c++) acc[a][c] = 0.f;

    int nk = (L + 7) / 8;

    {
        float4 av = ldxp4(base, i0 + lr, lh, N, L);
        float4 bv = ldxp4(base, j0 + lr, lh, N, L);
        As[0][lh + 0][lr] = av.x; As[0][lh + 1][lr] = av.y;
        As[0][lh + 2][lr] = av.z; As[0][lh + 3][lr] = av.w;
        Bs[0][lh + 0][lr] = bv.x; Bs[0][lh + 1][lr] = bv.y;
        Bs[0][lh + 2][lr] = bv.z; Bs[0][lh + 3][lr] = bv.w;
    }
    __syncthreads();

    int buf = 0;
    for (int kc = 0; kc < nk; kc++) {
        float4 an, bn;
        bool has = (kc + 1 < nk);
        if (has) {
            an = ldxp4(base, i0 + lr, (kc + 1) * 8 + lh, N, L);
            bn = ldxp4(base, j0 + lr, (kc + 1) * 8 + lh, N, L);
        }
#pragma unroll
        for (int k = 0; k < 8; k++) {
            float4 ra0 = *(const float4*)&As[buf][k][ty * 8];
            float4 ra1 = *(const float4*)&As[buf][k][ty * 8 + 4];
            float4 rb0 = *(const float4*)&Bs[buf][k][tx * 8];
            float4 rb1 = *(const float4*)&Bs[buf][k][tx * 8 + 4];
            float ra[8] = {ra0.x, ra0.y, ra0.z, ra0.w, ra1.x, ra1.y, ra1.z, ra1.w};
            float rb[8] = {rb0.x, rb0.y, rb0.z, rb0.w, rb1.x, rb1.y, rb1.z, rb1.w};
#pragma unroll
            for (int a = 0; a < 8; a++)
#pragma unroll
                for (int c = 0; c < 8; c++)
                    acc[a][c] += ra[a] * rb[c];
        }
        if (has) {
            int nb2 = buf ^ 1;
            As[nb2][lh + 0][lr] = an.x; As[nb2][lh + 1][lr] = an.y;
            As[nb2][lh + 2][lr] = an.z; As[nb2][lh + 3][lr] = an.w;
            Bs[nb2][lh + 0][lr] = bn.x; Bs[nb2][lh + 1][lr] = bn.y;
            Bs[nb2][lh + 2][lr] = bn.z; Bs[nb2][lh + 3][lr] = bn.w;
        }
        __syncthreads();
        buf ^= 1;
    }

    const float INF = 3.4e38f;

    // =========== Phase A: statistics for i-rows over the 128 j-columns ==========
    {
        // P1: strip min
#pragma unroll
        for (int a = 0; a < 8; a++) {
            float m1 = INF;
#pragma unroll
            for (int c = 0; c < 8; c++)
                if (j0 + tx * 8 + c < N) m1 = fminf(m1, acc[a][c]);
            sred[ty * 8 + a][tx] = m1;
        }
        __syncthreads();
        if (tid < 128) {
            float m = sred[tid][0];
#pragma unroll
            for (int q = 1; q < 16; q++) m = fminf(m, sred[tid][q]);
            sminA[tid] = m;
            if (i0 + tid < N)
                g_pmin[(size_t)(b * N + i0 + tid) * MAX_NB + bj] = m;
        }
        __syncthreads();
        // P2: strip second-distinct min
#pragma unroll
        for (int a = 0; a < 8; a++) {
            float m1 = INF, m2 = INF;
#pragma unroll
            for (int c = 0; c < 8; c++) {
                if (j0 + tx * 8 + c < N) {
                    float v = acc[a][c];
                    if (v < m1) { m2 = m1; m1 = v; }
                    else if (v > m1 && v < m2) m2 = v;
                }
            }
            float sm = sminA[ty * 8 + a];
            sred[ty * 8 + a][tx] = (m1 == sm) ? m2 : m1;
        }
        __syncthreads();
        if (tid < 128 && i0 + tid < N) {
            float m = sred[tid][0];
#pragma unroll
            for (int q = 1; q < 16; q++) m = fminf(m, sred[tid][q]);
            g_pmin2[(size_t)(b * N + i0 + tid) * MAX_NB + bj] = m;
        }
        __syncthreads();
        // P3: strip max
#pragma unroll
        for (int a = 0; a < 8; a++) {
            float m1 = -INF;
#pragma unroll
            for (int c = 0; c < 8; c++)
                if (j0 + tx * 8 + c < N) m1 = fmaxf(m1, acc[a][c]);
            sred[ty * 8 + a][tx] = m1;
        }
        __syncthreads();
        if (tid < 128 && i0 + tid < N) {
            float m = sred[tid][0];
#pragma unroll
            for (int q = 1; q < 16; q++) m = fmaxf(m, sred[tid][q]);
            g_pmax[(size_t)(b * N + i0 + tid) * MAX_NB + bj] = m;
        }
        __syncthreads();
        // P4+P5: count of strip-min, min index
#pragma unroll
        for (int a = 0; a < 8; a++) {
            float sm = sminA[ty * 8 + a];
            int cnt = 0, idx = 0x7fffffff;
#pragma unroll
            for (int c = 0; c < 8; c++) {
                int gcol = j0 + tx * 8 + c;
                if (gcol < N && acc[a][c] == sm) { cnt++; idx = min(idx, gcol); }
            }
            sredi[ty * 8 + a][tx] = cnt;
            sred[ty * 8 + a][tx] = __int_as_float(idx);
        }
        __syncthreads();
        if (tid < 128 && i0 + tid < N) {
            int cs = 0, ix = 0x7fffffff;
#pragma unroll
            for (int q = 0; q < 16; q++) {
                cs += sredi[tid][q];
                ix = min(ix, __float_as_int(sred[tid][q]));
            }
            size_t o = (size_t)(b * N + i0 + tid) * MAX_NB + bj;
            g_pcnt[o] = cs;
            g_pidx[o] = ix;
        }
        __syncthreads();
    }

    // =========== Phase B (mirror): statistics for j-rows over the 128 i-columns ==
    if (bi != bj) {
        // P1: strip min
#pragma unroll
        for (int c = 0; c < 8; c++) {
            float m1 = INF;
#pragma unroll
            for (int a = 0; a < 8; a++)
                if (i0 + ty * 8 + a < N) m1 = fminf(m1, acc[a][c]);
            sred[tx * 8 + c][ty] = m1;
        }
        __syncthreads();
        if (tid < 128) {
            float m = sred[tid][0];
#pragma unroll
            for (int q = 1; q < 16; q++) m = fminf(m, sred[tid][q]);
            sminA[tid] = m;
            if (j0 + tid < N)
                g_pmin[(size_t)(b * N + j0 + tid) * MAX_NB + bi] = m;
        }
        __syncthreads();
        // P2
#pragma unroll
        for (int c = 0; c < 8; c++) {
            float m1 = INF, m2 = INF;
#pragma unroll
            for (int a = 0; a < 8; a++) {
                if (i0 + ty * 8 + a < N) {
                    float v = acc[a][c];
                    if (v < m1) { m2 = m1; m1 = v; }
                    else if (v > m1 && v < m2) m2 = v;
                }
            }
            float sm = sminA[tx * 8 + c];
            sred[tx * 8 + c][ty] = (m1 == sm) ? m2 : m1;
        }
        __syncthreads();
        if (tid < 128 && j0 + tid < N) {
            float m = sred[tid][0];
#pragma unroll
            for (int q = 1; q < 16; q++) m = fminf(m, sred[tid][q]);
            g_pmin2[(size_t)(b * N + j0 + tid) * MAX_NB + bi] = m;
        }
        __syncthreads();
        // P3
#pragma unroll
        for (int c = 0; c < 8; c++) {
            float m1 = -INF;
#pragma unroll
            for (int a = 0; a < 8; a++)
                if (i0 + ty * 8 + a < N) m1 = fmaxf(m1, acc[a][c]);
            sred[tx * 8 + c][ty] = m1;
        }
        __syncthreads();
        if (tid < 128 && j0 + tid < N) {
            float m = sred[tid][0];
#pragma unroll
            for (int q = 1; q < 16; q++) m = fmaxf(m, sred[tid][q]);
            g_pmax[(size_t)(b * N + j0 + tid) * MAX_NB + bi] = m;
        }
        __syncthreads();
        // P4+P5
#pragma unroll
        for (int c = 0; c < 8; c++) {
            float sm = sminA[tx * 8 + c];
            int cnt = 0, idx = 0x7fffffff;
#pragma unroll
            for (int a = 0; a < 8; a++) {
                int gcol = i0 + ty * 8 + a;
                if (gcol < N && acc[a][c] == sm) { cnt++; idx = min(idx, gcol); }
            }
            sredi[tx * 8 + c][ty] = cnt;
            sred[tx * 8 + c][ty] = __int_as_float(idx);
        }
        __syncthreads();
        if (tid < 128 && j0 + tid < N) {
            int cs = 0, ix = 0x7fffffff;
#pragma unroll
            for (int q = 0; q < 16; q++) {
                cs += sredi[tid][q];
                ix = min(ix, __float_as_int(sred[tid][q]));
            }
            size_t o = (size_t)(b * N + j0 + tid) * MAX_NB + bi;
            g_pcnt[o] = cs;
            g_pidx[o] = ix;
        }
    }
}

// ---------- Kernel 3: merge strip stats -> argmin + exactness flag per row ------
__global__ void merge_kernel(int BN, int N, int nb, int K) {
    int n = blockIdx.x * 256 + threadIdx.x;
    if (n >= BN) return;
    const float INF = 3.4e38f;
    float m1 = INF, m2 = INF, mx = -INF;
    int cnt = 0, idx = 0x7fffffff;
    size_t base = (size_t)n * MAX_NB;
    for (int s = 0; s < nb; s++) {
        float pm  = g_pmin[base + s];
        float pm2 = g_pmin2[base + s];
        float px  = g_pmax[base + s];
        int   pc  = g_pcnt[base + s];
        int   pi  = g_pidx[base + s];
        mx = fmaxf(mx, px);
        if (pm < m1) {
            m2 = fminf(m1, pm2);
            m1 = pm; cnt = pc; idx = pi;
        } else if (pm == m1) {
            cnt += pc; idx = min(idx, pi);
            m2 = fminf(m2, pm2);
        } else {
            m2 = fminf(m2, pm);
        }
    }
    bool ok = (m1 < 0.f)
           && (-m1 > (mx + 256.f) * 1e-19f)
           && (m2 - m1 > 3e-17f)
           && (cnt == 1)
           && (N > K);
    g_flags[n]  = ok ? 0 : 1;
    g_argmin[n] = idx;
}

// ---------- Kernel 4: one-hot attention fill + h gather (write-only) ------------
__global__ void fill_kernel(float* __restrict__ h_out,
                            float* __restrict__ attn,
                            int N, int L) {
    int n = blockIdx.x;
    if (g_flags[n]) return;
    int b = n / N;
    int idx = g_argmin[n];
    int t = threadIdx.x;
    float* row = attn + (size_t)n * N;

    // zero-fill with the single 1.0
    for (int m = t * 4; m < N; m += 256 * 4) {
        float4 v = make_float4(0.f, 0.f, 0.f, 0.f);
        if (idx >= m && idx < m + 4) {
            if (idx == m)     v.x = 1.f;
            if (idx == m + 1) v.y = 1.f;
            if (idx == m + 2) v.z = 1.f;
            if (idx == m + 3) v.w = 1.f;
        }
        if (m + 3 < N) *(float4*)(row + m) = v;
        else for (int q = 0; q < 4 && m + q < N; q++) row[m + q] = (&v.x)[q];
    }
    // h row = x_proj[argmin]
    if (t < L) {
        const float* xpb = g_xp + (size_t)b * N * L;
        h_out[(size_t)n * L + t] = xpb[(size_t)idx * L + t];
    }
}

// ---------- Kernel 5: general fallback (flag-gated; recomputes score row) -------
__global__ void attn_slow_kernel(float* __restrict__ h_out,
                                 float* __restrict__ attn,
                                 int N, int L) {
    int n = blockIdx.x;
    if (g_flags[n] == 0) return;

    extern __shared__ unsigned su[];
    float* sf = (float*)su;
    __shared__ float xq[MAX_L];
    __shared__ float redf[256];
    __shared__ int   warp_tot[8];
    __shared__ int   s_cnt;
    __shared__ int   s_nnz;
    __shared__ int   ilist[1024];
    const int K = 100;

    int b = n / N;
    int diag = n - b * N;
    int t = threadIdx.x;
    int lane = t & 31, w = t >> 5;
    float* row = attn + (size_t)n * N;
    const float* xpb = g_xp + (size_t)b * N * L;

    // recompute this row's scores
    for (int l = t; l < L; l += 256) xq[l] = xpb[(size_t)diag * L + l];
    __syncthreads();
    for (int m = t; m < N; m += 256) {
        const float* xm = xpb + (size_t)m * L;
        float d = 0.f;
        for (int l = 0; l < L; l++) d += xq[l] * xm[l];
        su[m] = f2key(d);
    }
    __syncthreads();

    // radix select: key of K-th largest
    unsigned res = 0u;
    for (int bit = 31; bit >= 0; --bit) {
        unsigned cand = res | (1u << bit);
        if (t == 0) s_cnt = 0;
        __syncthreads();
        int c = 0;
        for (int m = t; m < N; m += 256) c += (su[m] >= cand) ? 1 : 0;
#pragma unroll
        for (int o = 16; o; o >>= 1) c += __shfl_down_sync(0xffffffffu, c, o);
        if (lane == 0) atomicAdd(&s_cnt, c);
        __syncthreads();
        if (s_cnt >= K) res = cand;
        __syncthreads();
    }

    if (t == 0) s_cnt = 0;
    __syncthreads();
    {
        int c = 0;
        for (int m = t; m < N; m += 256) c += (su[m] > res) ? 1 : 0;
#pragma unroll
        for (int o = 16; o; o >>= 1) c += __shfl_down_sync(0xffffffffu, c, o);
        if (lane == 0) atomicAdd(&s_cnt, c);
    }
    __syncthreads();
    int need = K - s_cnt;
    __syncthreads();

    int running = 0;
    float vmax = -3.4e38f;
    for (int m0 = 0; m0 < N; m0 += 256) {
        int m = m0 + t;
        bool valid = (m < N);
        unsigned u = valid ? su[m] : 0u;
        bool eq = valid && (u == res);
        unsigned ball = __ballot_sync(0xffffffffu, eq);
        if (lane == 0) warp_tot[w] = __popc(ball);
        __syncthreads();
        int woff = 0, ctot = 0;
#pragma unroll
        for (int i = 0; i < 8; i++) {
            int wt = warp_tot[i];
            ctot += wt;
            if (i < w) woff += wt;
        }
        int rank = running + woff + __popc(ball & ((1u << lane) - 1u));
        if (valid) {
            bool nb = (u > res) || (eq && rank < need) || (m == diag);
            float s = key2f(u);
            float v = nb ? s : (-1e19f * s);
            sf[m] = v;
            vmax = fmaxf(vmax, v);
        }
        running += ctot;
        __syncthreads();
    }

    redf[t] = vmax; __syncthreads();
#pragma unroll
    for (int st = 128; st; st >>= 1) { if (t < st) redf[t] = fmaxf(redf[t], redf[t + st]); __syncthreads(); }
    float M = redf[0]; __syncthreads();

    float lsum = 0.f;
    for (int m = t; m < N; m += 256) {
        float e = expf(sf[m] - M);
        sf[m] = e;
        lsum += e;
    }
    __syncthreads();
    redf[t] = lsum; __syncthreads();
#pragma unroll
    for (int st = 128; st; st >>= 1) { if (t < st) redf[t] += redf[t + st]; __syncthreads(); }
    float inv = 1.0f / redf[0]; __syncthreads();

    if (t == 0) s_nnz = 0;
    __syncthreads();
    for (int m = t; m < N; m += 256) {
        float a = sf[m] * inv;
        sf[m] = a;
        row[m] = a;
        if (a != 0.f) {
            int p = atomicAdd(&s_nnz, 1);
            if (p < 1024) ilist[p] = m;
        }
    }
    __syncthreads();
    int nnz = s_nnz;

    if (t < L) {
        float acc = 0.f;
        if (nnz == 1) {
            int m = ilist[0];
            acc = sf[m] * xpb[(size_t)m * L + t];
        } else {
            for (int m = 0; m < N; m++) {
                float a = sf[m];
                if (a != 0.f) acc += a * xpb[(size_t)m * L + t];
            }
        }
        h_out[(size_t)n * L + t] = acc;
    }
}

// ---------- launch ----------
extern "C" void kernel_launch(void* const* d_in, const int* in_sizes, int n_in,
                              void* d_out, int out_size) {
    const float* x = (const float*)d_in[0];
    const float* W = (const float*)d_in[1];

    int L = (int)(sqrt((double)in_sizes[1]) + 0.5);
    long long BN = in_sizes[0] / L;
    long long N  = (long long)out_size / BN - L;
    int Ni = (int)N;
    int B  = (int)(BN / N);
    int BNi = (int)BN;

    float* h_out = (float*)d_out;
    float* attn  = h_out + (size_t)BN * L;

    // 1) projection
    proj_kernel<<<(BNi + PROJ_ROWS - 1) / PROJ_ROWS, 256>>>(x, W, BNi, L);

    // 2) symmetric score GEMM with per-strip statistics (no S materialization)
    int nb = (Ni + 127) / 128;
    int tri = nb * (nb + 1) / 2;
    dim3 g2(tri, B);
    score_stats_kernel<<<g2, 256>>>(Ni, L, nb);

    // 3) merge stats -> argmin + flags
    merge_kernel<<<(BNi + 255) / 256, 256>>>(BNi, Ni, nb, 100);

    // 4) one-hot fill + h gather
    fill_kernel<<<BNi, 256>>>(h_out, attn, Ni, L);

    // 5) guarded general fallback (recomputes score rows; normally zero work)
    size_t smem = (size_t)Ni * sizeof(float);
    attn_slow_kernel<<<BNi, 256, smem>>>(h_out, attn, Ni, L);
}